// round 5
// baseline (speedup 1.0000x reference)
#include <cuda_runtime.h>
#include <cuda_fp16.h>
#include <cstdint>

// ============================================================
// Problem: out[B,256] = relu(X[B,1024] @ W^T + c)
//   X = [text | image], W/c precomputed from small weights.
//   B = 65536, H = 256, K = 1024.
// ============================================================
#define HDIM 256
#define KTOT 1024

// ---------------- device scratch ----------------
__device__ float  g_M1[HDIM * HDIM];
__device__ float  g_G1[HDIM * HDIM];
__device__ float  g_G2[HDIM * HDIM];
__device__ __half g_W16[HDIM * KTOT];   // fused weight, fp16, [256 rows][1024 k]
__device__ float  g_b1[HDIM];
__device__ float  g_c[HDIM];

// ---------------- PTX helpers ----------------
__device__ __forceinline__ uint32_t smem_u32(const void* p) {
    uint32_t a;
    asm("{ .reg .u64 t; cvta.to.shared.u64 t, %1; cvt.u32.u64 %0, t; }"
        : "=r"(a) : "l"(p));
    return a;
}

#define SW(x) ((x) ^ (((x) >> 3) & 0x70))

#define LDSM_X4(r0, r1, r2, r3, addr) \
    asm volatile("ldmatrix.sync.aligned.m8n8.x4.shared.b16 {%0,%1,%2,%3}, [%4];\n" \
        : "=r"(r0), "=r"(r1), "=r"(r2), "=r"(r3) : "r"(addr))

#define MMA16816(d, a, b0_, b1_) \
    asm volatile("mma.sync.aligned.m16n8k16.row.col.f32.f16.f16.f32 " \
        "{%0,%1,%2,%3}, {%4,%5,%6,%7}, {%8,%9}, {%0,%1,%2,%3};\n" \
        : "+f"((d)[0]), "+f"((d)[1]), "+f"((d)[2]), "+f"((d)[3]) \
        : "r"((a)[0]), "r"((a)[1]), "r"((a)[2]), "r"((a)[3]), "r"(b0_), "r"(b1_))

#define CP_ASYNC16(dst, src) \
    asm volatile("cp.async.cg.shared.global [%0], [%1], 16;\n" :: "r"(dst), "l"(src))
#define CP_COMMIT() asm volatile("cp.async.commit_group;\n")
#define CP_WAIT0()  asm volatile("cp.async.wait_group 0;\n" ::: "memory")

// ============================================================
// Precompute GEMMs: 64x64 tiles, 4x4 per thread, 256 threads
// ============================================================
template<bool HALF_OUT>
__device__ __forceinline__ void gemm64_body(const float* __restrict__ A, int lda,
                                            const float* __restrict__ B, int ldb,
                                            void* __restrict__ C, int ldc, int K,
                                            int i0, int j0) {
    __shared__ float As[32][72];   // As[k][m] (transposed), 288B rows (16B aligned)
    __shared__ float Bs[32][72];   // Bs[k][n]
    const int t = threadIdx.x;
    const int tx = t & 15, ty = t >> 4;
    float acc[4][4] = {};

    for (int k0 = 0; k0 < K; k0 += 32) {
        #pragma unroll
        for (int u = 0; u < 8; u++) {
            int idx = t + u * 256;             // 0..2047
            int ra = idx >> 5, ca = idx & 31;  // 64 rows x 32 k
            As[ca][ra] = A[(size_t)(i0 + ra) * lda + k0 + ca];
            int rb = idx >> 6, cb = idx & 63;  // 32 k x 64 cols
            Bs[rb][cb] = B[(size_t)(k0 + rb) * ldb + j0 + cb];
        }
        __syncthreads();
        #pragma unroll
        for (int k = 0; k < 32; k++) {
            float4 a4 = *(const float4*)&As[k][ty * 4];
            float4 b4 = *(const float4*)&Bs[k][tx * 4];
            acc[0][0] += a4.x * b4.x; acc[0][1] += a4.x * b4.y;
            acc[0][2] += a4.x * b4.z; acc[0][3] += a4.x * b4.w;
            acc[1][0] += a4.y * b4.x; acc[1][1] += a4.y * b4.y;
            acc[1][2] += a4.y * b4.z; acc[1][3] += a4.y * b4.w;
            acc[2][0] += a4.z * b4.x; acc[2][1] += a4.z * b4.y;
            acc[2][2] += a4.z * b4.z; acc[2][3] += a4.z * b4.w;
            acc[3][0] += a4.w * b4.x; acc[3][1] += a4.w * b4.y;
            acc[3][2] += a4.w * b4.z; acc[3][3] += a4.w * b4.w;
        }
        __syncthreads();
    }
    #pragma unroll
    for (int r = 0; r < 4; r++)
        #pragma unroll
        for (int c = 0; c < 4; c++) {
            size_t o = (size_t)(i0 + ty * 4 + r) * ldc + j0 + tx * 4 + c;
            if (HALF_OUT) ((__half*)C)[o] = __float2half_rn(acc[r][c]);
            else          ((float*)C)[o]  = acc[r][c];
        }
}

// Launch 1: z=0 -> M1 = Wo @ Wv (4x4 tiles of 64); z=1, block(0,0) -> b1 = Wo@bv + bo
__global__ void k_M1(const float* __restrict__ Wo, const float* __restrict__ Wv,
                     const float* __restrict__ in_proj_b,
                     const float* __restrict__ out_proj_b) {
    if (blockIdx.z == 1) {
        if (blockIdx.x | blockIdx.y) return;
        const int i = threadIdx.x;
        const float4* w  = (const float4*)(Wo + i * HDIM);
        const float4* bv = (const float4*)(in_proj_b + 2 * HDIM);
        float s = 0.f;
        #pragma unroll 8
        for (int k = 0; k < 64; k++) {
            float4 a = __ldg(&w[k]), b = __ldg(&bv[k]);
            s += a.x * b.x + a.y * b.y + a.z * b.z + a.w * b.w;
        }
        g_b1[i] = s + out_proj_b[i];
        return;
    }
    gemm64_body<false>(Wo, 256, Wv, 256, g_M1, 256, 256,
                       blockIdx.y * 64, blockIdx.x * 64);
}

// Launch 2: z=0: G1 = Wf1 @ M1 ; z=1: G2 = Wf2 @ M1
__global__ void k_G(const float* __restrict__ W_fuse) {
    const float* A = W_fuse + blockIdx.z * 256;
    float* C = blockIdx.z ? g_G2 : g_G1;
    gemm64_body<false>(A, 512, g_M1, 256, C, 256, 256,
                       blockIdx.y * 64, blockIdx.x * 64);
}

// Launch 3: z=0: W[:, :512] = G2 @ W_text ; z=1: W[:, 512:] = G1 @ W_img (fp16)
//           z=2, block(0,0): c = G1@b_img + G2@b_text + (Wf1+Wf2)@b1 + b_fuse
__global__ void k_W(const float* __restrict__ W_text, const float* __restrict__ W_img,
                    const float* __restrict__ W_fuse,
                    const float* __restrict__ b_text, const float* __restrict__ b_img,
                    const float* __restrict__ b_fuse) {
    if (blockIdx.z == 2) {
        if (blockIdx.x | blockIdx.y) return;
        const int i = threadIdx.x;
        const float4* g1 = (const float4*)(g_G1 + i * HDIM);
        const float4* g2 = (const float4*)(g_G2 + i * HDIM);
        const float4* w1 = (const float4*)(W_fuse + i * 512);
        const float4* w2 = (const float4*)(W_fuse + i * 512 + 256);
        const float4* vi = (const float4*)b_img;
        const float4* vt = (const float4*)b_text;
        const float4* v1 = (const float4*)g_b1;
        float s = b_fuse[i];
        #pragma unroll 4
        for (int k = 0; k < 64; k++) {
            float4 a = __ldg(&g1[k]), b = __ldg(&vi[k]);
            s += a.x * b.x + a.y * b.y + a.z * b.z + a.w * b.w;
            a = __ldg(&g2[k]); b = __ldg(&vt[k]);
            s += a.x * b.x + a.y * b.y + a.z * b.z + a.w * b.w;
            float4 c1 = __ldg(&w1[k]), c2 = __ldg(&w2[k]); b = v1[k];
            s += (c1.x + c2.x) * b.x + (c1.y + c2.y) * b.y
               + (c1.z + c2.z) * b.z + (c1.w + c2.w) * b.w;
        }
        g_c[i] = s;
        return;
    }
    const int z = blockIdx.z;
    const float* A = z ? g_G1 : g_G2;
    const float* B = z ? W_img : W_text;
    __half* C = g_W16 + z * 512;
    gemm64_body<true>(A, 256, B, 512, C, 1024, 256,
                      blockIdx.y * 64, blockIdx.x * 64);
}

// ============================================================
// Main GEMM: CTA 128x256, 8 warps of 64x64, K-chunk 64,
// double-buffered smem + software-pipelined fragments
// ============================================================
#define STAGE 49152                    // 16KB A + 32KB B
#define DYNSMEM (1024 + 1024 + 2 * STAGE)

__global__ void __launch_bounds__(256, 1)
fused_gemm(const float* __restrict__ text, const float* __restrict__ image,
           float* __restrict__ out) {
    extern __shared__ char smem_raw[];
    char* dsm = (char*)(((uintptr_t)smem_raw + 1023) & ~(uintptr_t)1023);
    const uint32_t sb = smem_u32(dsm);
    const int tid = threadIdx.x;
    const int lane = tid & 31;
    const int wid = tid >> 5;
    const int wm = wid & 1;            // 2 m-blocks of 64
    const int wn = wid >> 1;           // 4 n-blocks of 64
    const int mblk = blockIdx.x;

    float* bias_s = (float*)dsm;
    bias_s[tid] = g_c[tid];

    const float* srcT = text  + (size_t)mblk * 128 * 512;
    const float* srcI = image + (size_t)mblk * 128 * 512;

    const int a_c4 = tid & 15, a_r0 = tid >> 4;   // A tile: r = a_r0 + u*16
    const int b_c16 = tid & 7, b_r0 = tid >> 3;   // B tile: r = b_r0 + u*32

    // -------- prologue: chunk 0 --------
    float4 fa[8];
    #pragma unroll
    for (int u = 0; u < 8; u++)
        fa[u] = __ldg((const float4*)(srcT + (size_t)(a_r0 + u * 16) * 512 + a_c4 * 4));
    {
        uint32_t Bb = sb + 1024 + 16384;
        #pragma unroll
        for (int u = 0; u < 8; u++) {
            int r = b_r0 + u * 32;
            uint32_t dst = Bb + SW((uint32_t)(r * 128 + b_c16 * 16));
            CP_ASYNC16(dst, g_W16 + (size_t)r * 1024 + b_c16 * 8);
        }
        CP_COMMIT();
    }
    {
        char* Ab = dsm + 1024;
        #pragma unroll
        for (int u = 0; u < 8; u++) {
            int r = a_r0 + u * 16;
            uint32_t off = SW((uint32_t)(r * 128 + a_c4 * 8));
            __half2 h0 = __floats2half2_rn(fa[u].x, fa[u].y);
            __half2 h1 = __floats2half2_rn(fa[u].z, fa[u].w);
            *(uint2*)(Ab + off) = make_uint2(*(uint32_t*)&h0, *(uint32_t*)&h1);
        }
    }
    CP_WAIT0();
    __syncthreads();

    float acc[4][8][4] = {};

    const uint32_t xorv  = (uint32_t)((lane & 7) << 4);
    const int      rl    = lane & 15;
    const uint32_t khalf = (uint32_t)(((lane >> 4) & 1) * 16);

    #pragma unroll 1
    for (int kc = 0; kc < 16; kc++) {
        const int cur = kc & 1;
        const int nxt = cur ^ 1;

        // ---- prefetch next chunk: A -> regs, B -> cp.async ----
        if (kc < 15) {
            const int kn = kc + 1;
            const float* src = (kn < 8) ? srcT : srcI;
            const int kl = (kn & 7) * 64;
            #pragma unroll
            for (int u = 0; u < 8; u++)
                fa[u] = __ldg((const float4*)(src + (size_t)(a_r0 + u * 16) * 512 + kl + a_c4 * 4));
            uint32_t Bb = sb + 1024 + nxt * STAGE + 16384;
            #pragma unroll
            for (int u = 0; u < 8; u++) {
                int r = b_r0 + u * 32;
                uint32_t dst = Bb + SW((uint32_t)(r * 128 + b_c16 * 16));
                CP_ASYNC16(dst, g_W16 + (size_t)r * 1024 + kn * 64 + b_c16 * 8);
            }
            CP_COMMIT();
        }

        // ---- compute on cur (software-pipelined fragments) ----
        const uint32_t Ab = sb + 1024 + cur * STAGE;
        const uint32_t Bb = Ab + 16384;
        #pragma unroll
        for (int ks = 0; ks < 4; ks++) {
            uint32_t af[4][4];
            uint32_t bfA[4], bfB[4];
            #pragma unroll
            for (int im = 0; im < 4; im++) {
                uint32_t addr = (Ab + (uint32_t)((wm * 64 + im * 16 + rl) * 128)
                                    + (uint32_t)(ks * 32) + khalf) ^ xorv;
                LDSM_X4(af[im][0], af[im][1], af[im][2], af[im][3], addr);
            }
            {   // first B group
                uint32_t addr = (Bb + (uint32_t)((wn * 64 + rl) * 128)
                                    + (uint32_t)(ks * 32) + khalf) ^ xorv;
                LDSM_X4(bfA[0], bfA[1], bfA[2], bfA[3], addr);
            }
            #pragma unroll
            for (int in_ = 0; in_ < 4; in_++) {
                uint32_t* bc = (in_ & 1) ? bfB : bfA;
                uint32_t* bn = (in_ & 1) ? bfA : bfB;
                if (in_ < 3) {   // rolling prefetch of next B group
                    uint32_t addr = (Bb + (uint32_t)((wn * 64 + (in_ + 1) * 16 + rl) * 128)
                                        + (uint32_t)(ks * 32) + khalf) ^ xorv;
                    LDSM_X4(bn[0], bn[1], bn[2], bn[3], addr);
                }
                #pragma unroll
                for (int im = 0; im < 4; im++) {
                    MMA16816(acc[im][2 * in_],     af[im], bc[0], bc[2]);
                    MMA16816(acc[im][2 * in_ + 1], af[im], bc[1], bc[3]);
                }
            }
        }

        // ---- stage A-next into smem, then close the stage ----
        if (kc < 15) {
            char* Abn = dsm + 1024 + nxt * STAGE;
            #pragma unroll
            for (int u = 0; u < 8; u++) {
                int r = a_r0 + u * 16;
                uint32_t off = SW((uint32_t)(r * 128 + a_c4 * 8));
                __half2 h0 = __floats2half2_rn(fa[u].x, fa[u].y);
                __half2 h1 = __floats2half2_rn(fa[u].z, fa[u].w);
                *(uint2*)(Abn + off) = make_uint2(*(uint32_t*)&h0, *(uint32_t*)&h1);
            }
            CP_WAIT0();
        }
        __syncthreads();
    }

    // -------- epilogue: + bias, relu, store --------
    const int g = lane >> 2;
    const int cpair = (lane & 3) * 2;
    #pragma unroll
    for (int im = 0; im < 4; im++) {
        int m0 = mblk * 128 + wm * 64 + im * 16 + g;
        #pragma unroll
        for (int j = 0; j < 8; j++) {
            int n = wn * 64 + j * 8 + cpair;
            float bv0 = bias_s[n], bv1 = bias_s[n + 1];
            float2 v0 = make_float2(fmaxf(acc[im][j][0] + bv0, 0.f),
                                    fmaxf(acc[im][j][1] + bv1, 0.f));
            float2 v1 = make_float2(fmaxf(acc[im][j][2] + bv0, 0.f),
                                    fmaxf(acc[im][j][3] + bv1, 0.f));
            *(float2*)(out + (size_t)m0 * 256 + n)       = v0;
            *(float2*)(out + (size_t)(m0 + 8) * 256 + n) = v1;
        }
    }
}

// ============================================================
// kernel_launch
// ============================================================
extern "C" void kernel_launch(void* const* d_in, const int* in_sizes, int n_in,
                              void* d_out, int out_size) {
    const float* text       = (const float*)d_in[0];
    const float* image      = (const float*)d_in[1];
    const float* W_text     = (const float*)d_in[2];
    const float* b_text     = (const float*)d_in[3];
    const float* W_img      = (const float*)d_in[4];
    const float* b_img      = (const float*)d_in[5];
    const float* in_proj_w  = (const float*)d_in[6];
    const float* in_proj_b  = (const float*)d_in[7];
    const float* out_proj_w = (const float*)d_in[8];
    const float* out_proj_b = (const float*)d_in[9];
    const float* W_fuse     = (const float*)d_in[10];
    const float* b_fuse     = (const float*)d_in[11];
    const int batch = in_sizes[0] / 512;

    // Precompute (3 launches, bias folded in):
    k_M1<<<dim3(4, 4, 2), 256>>>(out_proj_w, in_proj_w + 512 * 256,
                                 in_proj_b, out_proj_b);
    k_G <<<dim3(4, 4, 2), 256>>>(W_fuse);
    k_W <<<dim3(8, 4, 3), 256>>>(W_text, W_img, W_fuse, b_text, b_img, b_fuse);

    cudaFuncSetAttribute(fused_gemm, cudaFuncAttributeMaxDynamicSharedMemorySize, DYNSMEM);
    fused_gemm<<<batch / 128, 256, DYNSMEM>>>(text, image, (float*)d_out);
}

// round 6
// speedup vs baseline: 1.5672x; 1.5672x over previous
#include <cuda_runtime.h>
#include <cuda_fp16.h>
#include <cstdint>

// ============================================================
// Problem: out[B,256] = relu(X[B,1024] @ W^T + c)
//   X = [text | image], W/c precomputed from small weights.
//   B = 65536, H = 256, K = 1024.
// ============================================================
#define HDIM 256
#define KTOT 1024

// ---------------- device scratch ----------------
__device__ float  g_M1[HDIM * HDIM];
__device__ float  g_G1[HDIM * HDIM];
__device__ float  g_G2[HDIM * HDIM];
__device__ __half g_W16[HDIM * KTOT];   // fused weight, fp16, [256 rows][1024 k]
__device__ float  g_b1[HDIM];
__device__ float  g_c[HDIM];

// ---------------- PTX helpers ----------------
__device__ __forceinline__ uint32_t smem_u32(const void* p) {
    uint32_t a;
    asm("{ .reg .u64 t; cvta.to.shared.u64 t, %1; cvt.u32.u64 %0, t; }"
        : "=r"(a) : "l"(p));
    return a;
}

#define SW(x) ((x) ^ (((x) >> 3) & 0x70))

#define LDSM_X4(r0, r1, r2, r3, addr) \
    asm volatile("ldmatrix.sync.aligned.m8n8.x4.shared.b16 {%0,%1,%2,%3}, [%4];\n" \
        : "=r"(r0), "=r"(r1), "=r"(r2), "=r"(r3) : "r"(addr))

#define MMA16816(d, a, b0_, b1_) \
    asm volatile("mma.sync.aligned.m16n8k16.row.col.f32.f16.f16.f32 " \
        "{%0,%1,%2,%3}, {%4,%5,%6,%7}, {%8,%9}, {%0,%1,%2,%3};\n" \
        : "+f"((d)[0]), "+f"((d)[1]), "+f"((d)[2]), "+f"((d)[3]) \
        : "r"((a)[0]), "r"((a)[1]), "r"((a)[2]), "r"((a)[3]), "r"(b0_), "r"(b1_))

#define CP_ASYNC16(dst, src) \
    asm volatile("cp.async.cg.shared.global [%0], [%1], 16;\n" :: "r"(dst), "l"(src))
#define CP_COMMIT() asm volatile("cp.async.commit_group;\n")
#define CP_WAIT0()  asm volatile("cp.async.wait_group 0;\n" ::: "memory")

// ============================================================
// Precompute GEMMs: 64x64 tiles, 4x4 per thread, 256 threads
// ============================================================
template<bool HALF_OUT>
__device__ __forceinline__ void gemm64_body(const float* __restrict__ A, int lda,
                                            const float* __restrict__ B, int ldb,
                                            void* __restrict__ C, int ldc, int K,
                                            int i0, int j0) {
    __shared__ float As[32][72];   // As[k][m] (transposed)
    __shared__ float Bs[32][72];   // Bs[k][n]
    const int t = threadIdx.x;
    const int tx = t & 15, ty = t >> 4;
    float acc[4][4] = {};

    for (int k0 = 0; k0 < K; k0 += 32) {
        #pragma unroll
        for (int u = 0; u < 8; u++) {
            int idx = t + u * 256;             // 0..2047
            int ra = idx >> 5, ca = idx & 31;  // 64 rows x 32 k
            As[ca][ra] = A[(size_t)(i0 + ra) * lda + k0 + ca];
            int rb = idx >> 6, cb = idx & 63;  // 32 k x 64 cols
            Bs[rb][cb] = B[(size_t)(k0 + rb) * ldb + j0 + cb];
        }
        __syncthreads();
        #pragma unroll
        for (int k = 0; k < 32; k++) {
            float4 a4 = *(const float4*)&As[k][ty * 4];
            float4 b4 = *(const float4*)&Bs[k][tx * 4];
            acc[0][0] += a4.x * b4.x; acc[0][1] += a4.x * b4.y;
            acc[0][2] += a4.x * b4.z; acc[0][3] += a4.x * b4.w;
            acc[1][0] += a4.y * b4.x; acc[1][1] += a4.y * b4.y;
            acc[1][2] += a4.y * b4.z; acc[1][3] += a4.y * b4.w;
            acc[2][0] += a4.z * b4.x; acc[2][1] += a4.z * b4.y;
            acc[2][2] += a4.z * b4.z; acc[2][3] += a4.z * b4.w;
            acc[3][0] += a4.w * b4.x; acc[3][1] += a4.w * b4.y;
            acc[3][2] += a4.w * b4.z; acc[3][3] += a4.w * b4.w;
        }
        __syncthreads();
    }
    #pragma unroll
    for (int r = 0; r < 4; r++)
        #pragma unroll
        for (int c = 0; c < 4; c++) {
            size_t o = (size_t)(i0 + ty * 4 + r) * ldc + j0 + tx * 4 + c;
            if (HALF_OUT) ((__half*)C)[o] = __float2half_rn(acc[r][c]);
            else          ((float*)C)[o]  = acc[r][c];
        }
}

// Launch 1: z=0 -> M1 = Wo @ Wv ; z=1, block(0,0) -> b1 = Wo@bv + bo
__global__ void k_M1(const float* __restrict__ Wo, const float* __restrict__ Wv,
                     const float* __restrict__ in_proj_b,
                     const float* __restrict__ out_proj_b) {
    if (blockIdx.z == 1) {
        if (blockIdx.x | blockIdx.y) return;
        const int i = threadIdx.x;
        const float4* w  = (const float4*)(Wo + i * HDIM);
        const float4* bv = (const float4*)(in_proj_b + 2 * HDIM);
        float s = 0.f;
        #pragma unroll 8
        for (int k = 0; k < 64; k++) {
            float4 a = __ldg(&w[k]), b = __ldg(&bv[k]);
            s += a.x * b.x + a.y * b.y + a.z * b.z + a.w * b.w;
        }
        g_b1[i] = s + out_proj_b[i];
        return;
    }
    gemm64_body<false>(Wo, 256, Wv, 256, g_M1, 256, 256,
                       blockIdx.y * 64, blockIdx.x * 64);
}

// Launch 2: z=0: G1 = Wf1 @ M1 ; z=1: G2 = Wf2 @ M1
__global__ void k_G(const float* __restrict__ W_fuse) {
    const float* A = W_fuse + blockIdx.z * 256;
    float* C = blockIdx.z ? g_G2 : g_G1;
    gemm64_body<false>(A, 512, g_M1, 256, C, 256, 256,
                       blockIdx.y * 64, blockIdx.x * 64);
}

// Launch 3: z=0: W[:, :512] = G2 @ W_text ; z=1: W[:, 512:] = G1 @ W_img (fp16)
//           z=2, block(0,0): c = G1@b_img + G2@b_text + (Wf1+Wf2)@b1 + b_fuse
__global__ void k_W(const float* __restrict__ W_text, const float* __restrict__ W_img,
                    const float* __restrict__ W_fuse,
                    const float* __restrict__ b_text, const float* __restrict__ b_img,
                    const float* __restrict__ b_fuse) {
    if (blockIdx.z == 2) {
        if (blockIdx.x | blockIdx.y) return;
        const int i = threadIdx.x;
        const float4* g1 = (const float4*)(g_G1 + i * HDIM);
        const float4* g2 = (const float4*)(g_G2 + i * HDIM);
        const float4* w1 = (const float4*)(W_fuse + i * 512);
        const float4* w2 = (const float4*)(W_fuse + i * 512 + 256);
        const float4* vi = (const float4*)b_img;
        const float4* vt = (const float4*)b_text;
        const float4* v1 = (const float4*)g_b1;
        float s = b_fuse[i];
        #pragma unroll 4
        for (int k = 0; k < 64; k++) {
            float4 a = __ldg(&g1[k]), b = __ldg(&vi[k]);
            s += a.x * b.x + a.y * b.y + a.z * b.z + a.w * b.w;
            a = __ldg(&g2[k]); b = __ldg(&vt[k]);
            s += a.x * b.x + a.y * b.y + a.z * b.z + a.w * b.w;
            float4 c1 = __ldg(&w1[k]), c2 = __ldg(&w2[k]); b = v1[k];
            s += (c1.x + c2.x) * b.x + (c1.y + c2.y) * b.y
               + (c1.z + c2.z) * b.z + (c1.w + c2.w) * b.w;
        }
        g_c[i] = s;
        return;
    }
    const int z = blockIdx.z;
    const float* A = z ? g_G1 : g_G2;
    const float* B = z ? W_img : W_text;
    __half* C = g_W16 + z * 512;
    gemm64_body<true>(A, 256, B, 512, C, 1024, 256,
                      blockIdx.y * 64, blockIdx.x * 64);
}

// ============================================================
// Main GEMM: CTA 128x256, 16 warps (512 thr), warp tile 32x64,
// K-chunk 64, double-buffered, round-4-style inner loop.
// 4 warps/SMSP for issue-latency hiding.
// ============================================================
#define STAGE 49152                    // 16KB A + 32KB B
#define DYNSMEM (1024 + 1024 + 2 * STAGE)

__global__ void __launch_bounds__(512, 1)
fused_gemm(const float* __restrict__ text, const float* __restrict__ image,
           float* __restrict__ out) {
    extern __shared__ char smem_raw[];
    char* dsm = (char*)(((uintptr_t)smem_raw + 1023) & ~(uintptr_t)1023);
    const uint32_t sb = smem_u32(dsm);
    const int tid = threadIdx.x;
    const int lane = tid & 31;
    const int wid = tid >> 5;          // 0..15
    const int wm = wid & 3;            // 4 m-blocks of 32
    const int wn = wid >> 2;           // 4 n-blocks of 64
    const int mblk = blockIdx.x;

    float* bias_s = (float*)dsm;
    if (tid < 256) bias_s[tid] = g_c[tid];

    const float* srcT = text  + (size_t)mblk * 128 * 512;
    const float* srcI = image + (size_t)mblk * 128 * 512;

    const int a_c4 = tid & 15, a_r0 = tid >> 4;   // A: rows a_r0 + u*32, u<4
    const int b_c16 = tid & 7, b_r0 = tid >> 3;   // B: rows b_r0 + u*64, u<4

    // -------- prologue: chunk 0 --------
    float4 fa[4];
    #pragma unroll
    for (int u = 0; u < 4; u++)
        fa[u] = __ldg((const float4*)(srcT + (size_t)(a_r0 + u * 32) * 512 + a_c4 * 4));
    {
        uint32_t Bb = sb + 1024 + 16384;
        #pragma unroll
        for (int u = 0; u < 4; u++) {
            int r = b_r0 + u * 64;
            uint32_t dst = Bb + SW((uint32_t)(r * 128 + b_c16 * 16));
            CP_ASYNC16(dst, g_W16 + (size_t)r * 1024 + b_c16 * 8);
        }
        CP_COMMIT();
    }
    {
        char* Ab = dsm + 1024;
        #pragma unroll
        for (int u = 0; u < 4; u++) {
            int r = a_r0 + u * 32;
            uint32_t off = SW((uint32_t)(r * 128 + a_c4 * 8));
            __half2 h0 = __floats2half2_rn(fa[u].x, fa[u].y);
            __half2 h1 = __floats2half2_rn(fa[u].z, fa[u].w);
            *(uint2*)(Ab + off) = make_uint2(*(uint32_t*)&h0, *(uint32_t*)&h1);
        }
    }
    CP_WAIT0();
    __syncthreads();

    float acc[2][8][4] = {};

    const uint32_t xorv  = (uint32_t)((lane & 7) << 4);
    const int      rl    = lane & 15;
    const uint32_t khalf = (uint32_t)(((lane >> 4) & 1) * 16);

    #pragma unroll 1
    for (int kc = 0; kc < 16; kc++) {
        const int cur = kc & 1;
        const int nxt = cur ^ 1;

        // ---- prefetch next chunk: A -> regs, B -> cp.async ----
        if (kc < 15) {
            const int kn = kc + 1;
            const float* src = (kn < 8) ? srcT : srcI;
            const int kl = (kn & 7) * 64;
            #pragma unroll
            for (int u = 0; u < 4; u++)
                fa[u] = __ldg((const float4*)(src + (size_t)(a_r0 + u * 32) * 512 + kl + a_c4 * 4));
            uint32_t Bb = sb + 1024 + nxt * STAGE + 16384;
            #pragma unroll
            for (int u = 0; u < 4; u++) {
                int r = b_r0 + u * 64;
                uint32_t dst = Bb + SW((uint32_t)(r * 128 + b_c16 * 16));
                CP_ASYNC16(dst, g_W16 + (size_t)r * 1024 + kn * 64 + b_c16 * 8);
            }
            CP_COMMIT();
        }

        // ---- compute on cur ----
        const uint32_t Ab = sb + 1024 + cur * STAGE;
        const uint32_t Bb = Ab + 16384;
        #pragma unroll
        for (int ks = 0; ks < 4; ks++) {
            uint32_t af[2][4];
            #pragma unroll
            for (int im = 0; im < 2; im++) {
                uint32_t addr = (Ab + (uint32_t)((wm * 32 + im * 16 + rl) * 128)
                                    + (uint32_t)(ks * 32) + khalf) ^ xorv;
                LDSM_X4(af[im][0], af[im][1], af[im][2], af[im][3], addr);
            }
            #pragma unroll
            for (int in_ = 0; in_ < 4; in_++) {
                uint32_t b0, b1, b2, b3;
                uint32_t addr = (Bb + (uint32_t)((wn * 64 + in_ * 16 + rl) * 128)
                                    + (uint32_t)(ks * 32) + khalf) ^ xorv;
                LDSM_X4(b0, b1, b2, b3, addr);
                #pragma unroll
                for (int im = 0; im < 2; im++) {
                    MMA16816(acc[im][2 * in_],     af[im], b0, b2);
                    MMA16816(acc[im][2 * in_ + 1], af[im], b1, b3);
                }
            }
        }

        // ---- stage A-next into smem, then close the stage ----
        if (kc < 15) {
            char* Abn = dsm + 1024 + nxt * STAGE;
            #pragma unroll
            for (int u = 0; u < 4; u++) {
                int r = a_r0 + u * 32;
                uint32_t off = SW((uint32_t)(r * 128 + a_c4 * 8));
                __half2 h0 = __floats2half2_rn(fa[u].x, fa[u].y);
                __half2 h1 = __floats2half2_rn(fa[u].z, fa[u].w);
                *(uint2*)(Abn + off) = make_uint2(*(uint32_t*)&h0, *(uint32_t*)&h1);
            }
            CP_WAIT0();
        }
        __syncthreads();
    }

    // -------- epilogue: + bias, relu, store --------
    const int g = lane >> 2;
    const int cpair = (lane & 3) * 2;
    #pragma unroll
    for (int im = 0; im < 2; im++) {
        int m0 = mblk * 128 + wm * 32 + im * 16 + g;
        #pragma unroll
        for (int j = 0; j < 8; j++) {
            int n = wn * 64 + j * 8 + cpair;
            float bv0 = bias_s[n], bv1 = bias_s[n + 1];
            float2 v0 = make_float2(fmaxf(acc[im][j][0] + bv0, 0.f),
                                    fmaxf(acc[im][j][1] + bv1, 0.f));
            float2 v1 = make_float2(fmaxf(acc[im][j][2] + bv0, 0.f),
                                    fmaxf(acc[im][j][3] + bv1, 0.f));
            *(float2*)(out + (size_t)m0 * 256 + n)       = v0;
            *(float2*)(out + (size_t)(m0 + 8) * 256 + n) = v1;
        }
    }
}

// ============================================================
// kernel_launch
// ============================================================
extern "C" void kernel_launch(void* const* d_in, const int* in_sizes, int n_in,
                              void* d_out, int out_size) {
    const float* text       = (const float*)d_in[0];
    const float* image      = (const float*)d_in[1];
    const float* W_text     = (const float*)d_in[2];
    const float* b_text     = (const float*)d_in[3];
    const float* W_img      = (const float*)d_in[4];
    const float* b_img      = (const float*)d_in[5];
    const float* in_proj_w  = (const float*)d_in[6];
    const float* in_proj_b  = (const float*)d_in[7];
    const float* out_proj_w = (const float*)d_in[8];
    const float* out_proj_b = (const float*)d_in[9];
    const float* W_fuse     = (const float*)d_in[10];
    const float* b_fuse     = (const float*)d_in[11];
    const int batch = in_sizes[0] / 512;

    // Precompute (3 launches, bias folded in):
    k_M1<<<dim3(4, 4, 2), 256>>>(out_proj_w, in_proj_w + 512 * 256,
                                 in_proj_b, out_proj_b);
    k_G <<<dim3(4, 4, 2), 256>>>(W_fuse);
    k_W <<<dim3(8, 4, 3), 256>>>(W_text, W_img, W_fuse, b_text, b_img, b_fuse);

    cudaFuncSetAttribute(fused_gemm, cudaFuncAttributeMaxDynamicSharedMemorySize, DYNSMEM);
    fused_gemm<<<batch / 128, 512, DYNSMEM>>>(text, image, (float*)d_out);
}